// round 11
// baseline (speedup 1.0000x reference)
#include <cuda_runtime.h>
#include <cuda_fp16.h>
#include <cstdint>

// Problem-shape maxima (S=128 segments, lengths in [1024,3072])
#define NMAX 393216
#define S_MAX 128
#define NCH 8          // attn chunks per segment
#define CROWS 384      // rows per attn chunk (8*384 = 3072 = max len)

__device__ float g_y[NMAX];
__device__ float g_z[NMAX];
__device__ float4 g_segp[S_MAX];
__device__ int   g_offv[S_MAX];
__device__ float g_part[S_MAX * NCH * 256];
__device__ int   g_cnt[S_MAX];   // zero-init at load; self-resetting per call

__device__ __forceinline__ float tanh_approx(float v) {
    float r;
    asm("tanh.approx.f32 %0, %1;" : "=f"(r) : "f"(v));
    return r;
}
__device__ __forceinline__ uint32_t smem_u32(const void* p) {
    uint32_t a;
    asm("{ .reg .u64 t; cvta.to.shared.u64 t, %1; cvt.u32.u64 %0, t; }" : "=r"(a) : "l"(p));
    return a;
}
__device__ __forceinline__ void ldm4(uint32_t* r, uint32_t addr) {
    asm volatile("ldmatrix.sync.aligned.m8n8.x4.shared.b16 {%0,%1,%2,%3}, [%4];"
        : "=r"(r[0]), "=r"(r[1]), "=r"(r[2]), "=r"(r[3]) : "r"(addr));
}
__device__ __forceinline__ void mma16816(float* c, const uint32_t* a, uint32_t b0, uint32_t b1) {
    asm volatile("mma.sync.aligned.m16n8k16.row.col.f32.f16.f16.f32 "
        "{%0,%1,%2,%3}, {%4,%5,%6,%7}, {%8,%9}, {%0,%1,%2,%3};"
        : "+f"(c[0]), "+f"(c[1]), "+f"(c[2]), "+f"(c[3])
        : "r"(a[0]), "r"(a[1]), "r"(a[2]), "r"(a[3]), "r"(b0), "r"(b1));
}
__device__ __forceinline__ void bar_pair(int id) {
    asm volatile("bar.sync %0, 64;" :: "r"(id) : "memory");
}
__device__ __forceinline__ uint32_t packh2(float2 v) {
    half2 h = __floats2half2_rn(v.x, v.y);
    return *(uint32_t*)&h;
}

// ---------------------------------------------------------------------------
// Kernel 1 (v9): persistent fused GEMM + head, HMMA, A DIRECT FROM GMEM.
//   256 threads / 8 warps, 2 blocks per SM. Warp pair (w, w+4) owns A-row
//   quarter wa = w&3 (32 rows); w<4 -> h[0:64), w>=4 -> h[64:128).
//   A fragments are built per-lane straight from global x (float2 LDG + cvt)
//   using the m16n8k16 layout: a0 = x[r0+lane/4, k+2(lane%4) ..+1], a1 = row+8,
//   a2/a3 = k+8. NO x staging, NO STS, NO barriers in the main loop -- warps
//   free-run; only W1 lives in smem (staged once). Row guard = min() clamp
//   (garbage rows are never stored).
// ---------------------------------------------------------------------------
#define WSTB 528          // W1 row stride, bytes (256 halves + 8 pad)
#define WST  264          // W1 row stride, halves
#define FOFF (128 * WSTB) // 67584
#define SMEM_K1 (FOFF + 512 + 1024 + 1024)

__global__ __launch_bounds__(256, 2) void gemm_head_kernel(
    const float* __restrict__ x, const float* __restrict__ W1,
    const float* __restrict__ b1, const float* __restrict__ W2,
    const float* __restrict__ b2, int N, int ntiles)
{
    extern __shared__ char smem[];
    half*   w1s = (half*)smem;                  // [128 h][WST k]
    float*  sb1 = (float*)(smem + FOFF);        // [128]
    float*  sw2 = sb1 + 128;                    // [256]
    float2* sEp = (float2*)(sw2 + 256);         // [128] pair exchange

    const int tid  = threadIdx.x;
    const int lane = tid & 31;
    const int w    = tid >> 5;        // 0..7
    const int wa   = w & 3;           // pair id / A-row quarter
    const int hb   = (w >> 2) * 8;    // h-tile base (units of 8 columns)
    const int barid = 1 + wa;

    // Stage W1 transposed (h-major, k contiguous) as fp16 — once per block
    for (int idx = tid; idx < 256 * 128; idx += 256) {
        int k = idx >> 7, h = idx & 127;
        w1s[h * WST + k] = __float2half(W1[idx]);
    }
    if (tid < 128) sb1[tid] = b1[tid];
    sw2[tid] = W2[tid];

    const float B20 = __ldg(b2), B21 = __ldg(b2 + 1);
    const int stride = gridDim.x;
    const float2* __restrict__ x2 = (const float2*)x;

    // B ldmatrix per-lane address (validated layout)
    const uint32_t sbase = smem_u32(smem);
    const uint32_t boffc = (lane >> 4) * (8 * WSTB) + (lane & 7) * WSTB + ((lane >> 3) & 1) * 16;
    const uint32_t blaneB = sbase + hb * (8 * WSTB) + boffc;

    const int laneR = lane >> 2;      // fragment row within group (0..7)
    const int laneC = lane & 3;       // float2 column within k8
    const int rA = laneR;             // epilogue aliases
    const int qq = laneC * 2;

    int t = blockIdx.x;
    __syncthreads();   // W1 staged (only block-wide sync)

    while (t < ntiles) {
        const int rowBase = t * 128;
        // clamped global rows for the 4 fragment row positions
        const int r00 = min(rowBase + wa * 32 + laneR,      N - 1);
        const int r01 = min(rowBase + wa * 32 + laneR + 8,  N - 1);
        const int r10 = min(rowBase + wa * 32 + laneR + 16, N - 1);
        const int r11 = min(rowBase + wa * 32 + laneR + 24, N - 1);
        const float2* p00 = x2 + (size_t)r00 * 128 + laneC;
        const float2* p01 = x2 + (size_t)r01 * 128 + laneC;
        const float2* p10 = x2 + (size_t)r10 * 128 + laneC;
        const float2* p11 = x2 + (size_t)r11 * 128 + laneC;

        float acc[8][2][4];
        #pragma unroll
        for (int i = 0; i < 8; i++)
            #pragma unroll
            for (int g = 0; g < 2; g++) {
                acc[i][g][0] = 0.f; acc[i][g][1] = 0.f;
                acc[i][g][2] = 0.f; acc[i][g][3] = 0.f;
            }

        #pragma unroll
        for (int ks = 0; ks < 16; ks++) {
            const int co = ks * 8;     // float2 offset of this k16 step
            uint32_t a0[4], a1[4];
            a0[0] = packh2(p00[co]);
            a0[1] = packh2(p01[co]);
            a0[2] = packh2(p00[co + 4]);
            a0[3] = packh2(p01[co + 4]);
            a1[0] = packh2(p10[co]);
            a1[1] = packh2(p11[co]);
            a1[2] = packh2(p10[co + 4]);
            a1[3] = packh2(p11[co + 4]);
            const uint32_t bab = blaneB + ks * 32;
            #pragma unroll
            for (int ntp = 0; ntp < 4; ntp++) {
                uint32_t bf[4];
                ldm4(bf, bab + ntp * (16 * WSTB));
                mma16816(acc[2*ntp    ][0], a0, bf[0], bf[1]);
                mma16816(acc[2*ntp    ][1], a1, bf[0], bf[1]);
                mma16816(acc[2*ntp + 1][0], a0, bf[2], bf[3]);
                mma16816(acc[2*ntp + 1][1], a1, bf[2], bf[3]);
            }
        }

        // Epilogue: tanh (MUFU) + H->2 projection; quad reduce; pair exchange
        float yv[2][2] = {{0.f,0.f},{0.f,0.f}};
        float zv[2][2] = {{0.f,0.f},{0.f,0.f}};
        #pragma unroll
        for (int nt = 0; nt < 8; nt++) {
            #pragma unroll
            for (int j = 0; j < 2; j++) {
                int h = (hb + nt) * 8 + qq + j;
                float bb = sb1[h], wva = sw2[2*h], wvb = sw2[2*h + 1];
                #pragma unroll
                for (int g = 0; g < 2; g++) {
                    float t0 = tanh_approx(acc[nt][g][j] + bb);
                    yv[g][0] += t0 * wva; zv[g][0] += t0 * wvb;
                    float t1 = tanh_approx(acc[nt][g][2 + j] + bb);
                    yv[g][1] += t1 * wva; zv[g][1] += t1 * wvb;
                }
            }
        }
        #pragma unroll
        for (int o = 1; o < 4; o <<= 1) {
            #pragma unroll
            for (int g = 0; g < 2; g++) {
                yv[g][0] += __shfl_xor_sync(0xffffffff, yv[g][0], o);
                zv[g][0] += __shfl_xor_sync(0xffffffff, zv[g][0], o);
                yv[g][1] += __shfl_xor_sync(0xffffffff, yv[g][1], o);
                zv[g][1] += __shfl_xor_sync(0xffffffff, zv[g][1], o);
            }
        }
        if (w >= 4 && (lane & 3) == 0) {
            #pragma unroll
            for (int g = 0; g < 2; g++) {
                sEp[wa*32 + g*16 + rA    ] = make_float2(yv[g][0], zv[g][0]);
                sEp[wa*32 + g*16 + rA + 8] = make_float2(yv[g][1], zv[g][1]);
            }
        }
        bar_pair(barid);
        if (w < 4 && (lane & 3) == 0) {
            #pragma unroll
            for (int g = 0; g < 2; g++) {
                float2 e0 = sEp[wa*32 + g*16 + rA];
                float2 e1 = sEp[wa*32 + g*16 + rA + 8];
                int gr0 = rowBase + wa*32 + g*16 + rA;
                int gr1 = gr0 + 8;
                if (gr0 < N) { g_y[gr0] = yv[g][0] + e0.x + B20; g_z[gr0] = zv[g][0] + e0.y + B21; }
                if (gr1 < N) { g_y[gr1] = yv[g][1] + e1.x + B20; g_z[gr1] = zv[g][1] + e1.y + B21; }
            }
        }
        bar_pair(barid);   // sEp consumed before the faster warp's next write
        t += stride;
    }
}

// ---------------------------------------------------------------------------
// Kernel 2: per-segment stats. |y| <= ||W2[:,0]||_1 ~ 11, so exp(y) is safe
// without max subtraction. Segment offsets via parallel scan.
// ---------------------------------------------------------------------------
__global__ __launch_bounds__(256) void seg_stats_kernel(const int* __restrict__ lengths, int S)
{
    __shared__ float sred[256];
    __shared__ float sbc[3];
    __shared__ int slen[S_MAX];
    const int s = blockIdx.x, tid = threadIdx.x;

    if (tid < S_MAX) slen[tid] = (tid < S) ? lengths[tid] : 0;
    __syncthreads();
    #pragma unroll
    for (int d = 1; d < S_MAX; d <<= 1) {
        int v = 0;
        if (tid < S_MAX && tid >= d) v = slen[tid - d];
        __syncthreads();
        if (tid < S_MAX) slen[tid] += v;
        __syncthreads();
    }
    const int off = (s == 0) ? 0 : slen[s - 1];
    const int len = lengths[s];
    const float invlen = 1.0f / (float)len;

    float wsum = 0.f, wx = 0.f, zs = 0.f;
    for (int i = tid; i < len; i += 256) {
        float wv = expf(g_y[off + i]);
        wsum += wv;
        wx   += wv * ((float)(i + 1) * invlen);
        zs   += g_z[off + i];
    }
    sred[tid] = wsum; __syncthreads();
    for (int o = 128; o > 0; o >>= 1) { if (tid < o) sred[tid] += sred[tid+o]; __syncthreads(); }
    if (tid == 0) sbc[0] = sred[0];
    __syncthreads();
    sred[tid] = wx; __syncthreads();
    for (int o = 128; o > 0; o >>= 1) { if (tid < o) sred[tid] += sred[tid+o]; __syncthreads(); }
    if (tid == 0) sbc[1] = sred[0];
    __syncthreads();
    sred[tid] = zs; __syncthreads();
    for (int o = 128; o > 0; o >>= 1) { if (tid < o) sred[tid] += sred[tid+o]; __syncthreads(); }
    if (tid == 0) sbc[2] = sred[0];
    __syncthreads();

    const float mu = sbc[1] / sbc[0];
    const float v  = sbc[2] * invlen;
    const float sd = (v > 20.f) ? v : log1pf(expf(v));   // softplus
    const float invsd = 1.0f / sd;

    float ps = 0.f;
    for (int i = tid; i < len; i += 256) {
        float xp = (float)(i + 1) * invlen;
        float d = (xp - mu) * invsd;
        ps += expf(-0.5f * d * d);
    }
    sred[tid] = ps; __syncthreads();
    for (int o = 128; o > 0; o >>= 1) { if (tid < o) sred[tid] += sred[tid+o]; __syncthreads(); }
    if (tid == 0) {
        float psum = sred[0] * (0.3989422804014327f * invsd);
        g_segp[s] = make_float4(mu, sd, psum, 0.f);
        g_offv[s] = off;
    }
}

// ---------------------------------------------------------------------------
// Kernel 3: attn per row + partial of out = seg_sum(attn*x), fused finalize.
//   fp32 x, Grid (NCH x S); 4 row-groups x 64 threads, float4 loads,
//   unroll-8. Last block per segment (atomic counter) sums the NCH
//   deterministic partials into out.
// ---------------------------------------------------------------------------
__global__ __launch_bounds__(256) void attn_out_kernel(
    const float* __restrict__ x, const int* __restrict__ lengths,
    float* __restrict__ attn_out, float* __restrict__ out)
{
    __shared__ float  sattn[256];
    __shared__ float4 sred4[256];
    __shared__ int slast;
    const int s = blockIdx.y, ch = blockIdx.x;
    const int tid = threadIdx.x;
    const int g = tid >> 6;
    const int c = tid & 63;
    const int len = lengths[s];
    const int off = g_offv[s];
    const float4 p = g_segp[s];
    const float mu = p.x, invsd = 1.0f / p.y, psum = p.z;
    const float invlen = 1.0f / (float)len;
    const float coef = 0.3989422804014327f * invsd / (psum + 0.001f);

    float4 acc = make_float4(0.f, 0.f, 0.f, 0.f);
    const int r0 = ch * CROWS;
    #pragma unroll
    for (int tb = 0; tb < CROWS; tb += 256) {
        const int tsz = (CROWS - tb < 256) ? (CROWS - tb) : 256;
        int rbase = r0 + tb;
        if (rbase >= len) break;
        int r = rbase + tid;
        float a = 0.f;
        if (tid < tsz && r < len) {
            float xp = (float)(r + 1) * invlen;
            float d = (xp - mu) * invsd;
            a = expf(-0.5f * d * d) * coef;
            attn_out[off + r] = a;
        }
        sattn[tid] = a;
        __syncthreads();
        int nrows = len - rbase; if (nrows > tsz) nrows = tsz;
        const float4* __restrict__ xp4 = (const float4*)(x + (size_t)(off + rbase) * 256) + c;
        int j = g;
        for (; j + 28 < nrows; j += 32) {
            float aa[8]; float4 vv[8];
            #pragma unroll
            for (int u = 0; u < 8; u++) { aa[u] = sattn[j + u*4]; vv[u] = xp4[(size_t)(j + u*4) * 64]; }
            #pragma unroll
            for (int u = 0; u < 8; u++) {
                acc.x += aa[u] * vv[u].x; acc.y += aa[u] * vv[u].y;
                acc.z += aa[u] * vv[u].z; acc.w += aa[u] * vv[u].w;
            }
        }
        for (; j < nrows; j += 4) {
            float a0 = sattn[j];
            float4 v0 = xp4[(size_t)j * 64];
            acc.x += a0 * v0.x; acc.y += a0 * v0.y; acc.z += a0 * v0.z; acc.w += a0 * v0.w;
        }
        __syncthreads();
    }
    sred4[tid] = acc;
    __syncthreads();
    if (g == 0) {
        float4 t0 = sred4[c], t1 = sred4[64 + c], t2 = sred4[128 + c], t3 = sred4[192 + c];
        float4 tot = make_float4(t0.x + t1.x + t2.x + t3.x,
                                 t0.y + t1.y + t2.y + t3.y,
                                 t0.z + t1.z + t2.z + t3.z,
                                 t0.w + t1.w + t2.w + t3.w);
        ((float4*)&g_part[(size_t)(s * NCH + ch) * 256])[c] = tot;
    }
    // ---- fused finalize: last chunk-block of this segment sums partials
    __threadfence();
    if (tid == 0) {
        int old = atomicAdd(&g_cnt[s], 1);
        slast = (old == NCH - 1);
    }
    __syncthreads();
    if (slast) {
        float v = 0.f;
        #pragma unroll
        for (int j = 0; j < NCH; j++) v += g_part[(size_t)(s * NCH + j) * 256 + tid];
        out[(size_t)s * 256 + tid] = v;
        if (tid == 0) g_cnt[s] = 0;   // reset for next graph replay
    }
}

// ---------------------------------------------------------------------------
extern "C" void kernel_launch(void* const* d_in, const int* in_sizes, int n_in,
                              void* d_out, int out_size)
{
    const float* x       = (const float*)d_in[0];
    const int*   lengths = (const int*)  d_in[1];
    const float* W1      = (const float*)d_in[2];
    const float* b1      = (const float*)d_in[3];
    const float* W2      = (const float*)d_in[4];
    const float* b2      = (const float*)d_in[5];

    const int N = in_sizes[0] / 256;
    const int S = in_sizes[1];

    float* out  = (float*)d_out;             // (S, 256)
    float* attn = out + (size_t)S * 256;     // (N, 1)

    cudaFuncSetAttribute(gemm_head_kernel,
                         cudaFuncAttributeMaxDynamicSharedMemorySize, SMEM_K1);

    int ntiles = (N + 127) / 128;
    int grid = ntiles < 296 ? ntiles : 296;   // 2 blocks/SM persistent
    gemm_head_kernel<<<grid, 256, SMEM_K1>>>(x, W1, b1, W2, b2, N, ntiles);
    seg_stats_kernel<<<S, 256>>>(lengths, S);
    attn_out_kernel<<<dim3(NCH, S), 256>>>(x, lengths, attn, out);
}

// round 12
// speedup vs baseline: 1.1934x; 1.1934x over previous
#include <cuda_runtime.h>
#include <cuda_fp16.h>
#include <cstdint>

// Problem-shape maxima (S=128 segments, lengths in [1024,3072])
#define NMAX 393216
#define S_MAX 128
#define NCH 8          // attn chunks per segment
#define CROWS 384      // rows per attn chunk (8*384 = 3072 = max len)

__device__ float g_y[NMAX];
__device__ float g_z[NMAX];
__device__ float4 g_segp[S_MAX];
__device__ int   g_offv[S_MAX];
__device__ float g_part[S_MAX * NCH * 256];
__device__ int   g_cnt[S_MAX];   // zero-init at load; self-resetting per call

__device__ __forceinline__ float tanh_approx(float v) {
    float r;
    asm("tanh.approx.f32 %0, %1;" : "=f"(r) : "f"(v));
    return r;
}
__device__ __forceinline__ uint32_t smem_u32(const void* p) {
    uint32_t a;
    asm("{ .reg .u64 t; cvta.to.shared.u64 t, %1; cvt.u32.u64 %0, t; }" : "=r"(a) : "l"(p));
    return a;
}
__device__ __forceinline__ void ldm4(uint32_t* r, uint32_t addr) {
    asm volatile("ldmatrix.sync.aligned.m8n8.x4.shared.b16 {%0,%1,%2,%3}, [%4];"
        : "=r"(r[0]), "=r"(r[1]), "=r"(r[2]), "=r"(r[3]) : "r"(addr));
}
__device__ __forceinline__ void mma16816(float* c, const uint32_t* a, uint32_t b0, uint32_t b1) {
    asm volatile("mma.sync.aligned.m16n8k16.row.col.f32.f16.f16.f32 "
        "{%0,%1,%2,%3}, {%4,%5,%6,%7}, {%8,%9}, {%0,%1,%2,%3};"
        : "+f"(c[0]), "+f"(c[1]), "+f"(c[2]), "+f"(c[3])
        : "r"(a[0]), "r"(a[1]), "r"(a[2]), "r"(a[3]), "r"(b0), "r"(b1));
}
__device__ __forceinline__ void bar_pair(int id) {
    asm volatile("bar.sync %0, 64;" :: "r"(id) : "memory");
}

// ---------------------------------------------------------------------------
// Kernel 1 (v10 = v7 + B-fragment double-buffering): persistent fused GEMM +
// head, HMMA + ldmatrix, PAIR-DECOUPLED.
//   256 threads / 8 warps, 2 blocks per SM. Warp pair (w, w+4) owns A-row
//   quarter wa = w&3 (32 rows); w<4 -> h[0:64), w>=4 -> h[64:128).
//   Pair-private A staging; bar.sync(1+wa, 64) only -- pairs run decoupled.
//   Double-buffered per-pair A chunks, LDG prefetch 2 chunks ahead.
//   NEW: B fragments double-buffered in registers: LDSM of bf(ntp+1) issues
//   before the MMAs of bf(ntp), hiding the ~30cyc LDSM->MMA latency (+4 regs).
// ---------------------------------------------------------------------------
#define XSTB 144          // x row stride, bytes (64 halves + 8 pad)
#define WSTB 528          // W1 row stride, bytes (256 halves + 8 pad)
#define WST  264          // W1 row stride, halves
#define XBUFB (128 * XSTB)           // 18432 bytes per x buffer
#define W1OFF (2 * XBUFB)            // 36864
#define FOFF  (W1OFF + 128 * WSTB)   // 104448
#define SMEM_K1 (FOFF + 512 + 1024 + 1024)

__global__ __launch_bounds__(256, 2) void gemm_head_kernel(
    const float* __restrict__ x, const float* __restrict__ W1,
    const float* __restrict__ b1, const float* __restrict__ W2,
    const float* __restrict__ b2, int N, int ntiles)
{
    extern __shared__ char smem[];
    half*   w1s = (half*)(smem + W1OFF);
    float*  sb1 = (float*)(smem + FOFF);
    float*  sw2 = sb1 + 128;
    float2* sEp = (float2*)(sw2 + 256);

    const int tid  = threadIdx.x;
    const int lane = tid & 31;
    const int w    = tid >> 5;       // 0..7
    const int wa   = w & 3;          // pair id / A-row quarter
    const int hb   = (w >> 2) * 8;   // h-tile base (units of 8 columns)
    const int barid = 1 + wa;

    // Stage W1 transposed (h-major, k contiguous) as fp16 — once per block
    for (int idx = tid; idx < 256 * 128; idx += 256) {
        int k = idx >> 7, h = idx & 127;
        w1s[h * WST + k] = __float2half(W1[idx]);
    }
    if (tid < 128) sb1[tid] = b1[tid];
    sw2[tid] = W2[tid];

    const float B20 = __ldg(b2), B21 = __ldg(b2 + 1);
    const int stride = gridDim.x;
    const float4* __restrict__ x4 = (const float4*)x;

    // LDG/STS pattern: pair (w, w+4) stages rows [wa*32, wa*32+32);
    // this warp handles 16 of them: 2 rows per iteration, 8 iterations.
    const int rbw = wa * 32 + (w >> 2) * 16 + (lane >> 4);  // + i*2
    const int ldq = lane & 15;                               // float4 col

    // ldmatrix per-lane address constants (validated)
    const uint32_t sbase = smem_u32(smem);
    const uint32_t aoffc = ((lane >> 3) & 1) * (8 * XSTB) + (lane & 7) * XSTB + (lane >> 4) * 16;
    const uint32_t boffc = (lane >> 4) * (8 * WSTB) + (lane & 7) * WSTB + ((lane >> 3) & 1) * 16;
    const uint32_t xlaneA = sbase + wa * 32 * XSTB + aoffc;
    const uint32_t blaneB = sbase + W1OFF + hb * (8 * WSTB) + boffc;

    const int rA = lane >> 2;         // epilogue row-in-group
    const int qq = (lane & 3) * 2;    // epilogue col pair

    uint2 ph[8];   // prefetched chunk, already fp16 (half2 pairs)
    int t = blockIdx.x;   // grid <= ntiles

    __syncthreads();   // W1 staged (only block-wide sync)

    // ---- prologue: buf0 <- chunk0(t); ph <- chunk1(t)
    #pragma unroll
    for (int i = 0; i < 8; i++) {
        int grow = t * 128 + rbw + i * 2;
        float4 v = (grow < N) ? x4[(size_t)grow * 64 + ldq]
                              : make_float4(0.f, 0.f, 0.f, 0.f);
        half2 h0 = __floats2half2_rn(v.x, v.y);
        half2 h1 = __floats2half2_rn(v.z, v.w);
        *(uint2*)(smem + (rbw + i * 2) * XSTB + ldq * 8) =
            make_uint2(*(uint32_t*)&h0, *(uint32_t*)&h1);
    }
    #pragma unroll
    for (int i = 0; i < 8; i++) {
        int grow = t * 128 + rbw + i * 2;
        float4 v = (grow < N) ? x4[(size_t)grow * 64 + 16 + ldq]
                              : make_float4(0.f, 0.f, 0.f, 0.f);
        half2 h0 = __floats2half2_rn(v.x, v.y);
        half2 h1 = __floats2half2_rn(v.z, v.w);
        ph[i] = make_uint2(*(uint32_t*)&h0, *(uint32_t*)&h1);
    }
    bar_pair(barid);   // buf0 visible to the pair

    while (t < ntiles) {
        const int rowBase = t * 128;
        float acc[8][2][4];
        #pragma unroll
        for (int i = 0; i < 8; i++)
            #pragma unroll
            for (int g = 0; g < 2; g++) {
                acc[i][g][0] = 0.f; acc[i][g][1] = 0.f;
                acc[i][g][2] = 0.f; acc[i][g][3] = 0.f;
            }

        #pragma unroll
        for (int kc = 0; kc < 4; kc++) {
            const int cur = kc & 1;
            // ---- STS: ph (chunk kc+1) -> other buffer (pair's rows only)
            int t1 = t; if (kc == 3) t1 = t + stride;
            if (t1 < ntiles) {
                char* xb = smem + (((kc + 1) & 1) * XBUFB);
                #pragma unroll
                for (int i = 0; i < 8; i++)
                    *(uint2*)(xb + (rbw + i * 2) * XSTB + ldq * 8) = ph[i];
            }
            // ---- LDG: chunk kc+2 -> ph (convert to fp16 at load)
            int t2 = t, c2 = kc + 2;
            if (kc >= 2) { t2 = t + stride; c2 = kc - 2; }
            if (t2 < ntiles) {
                int rb2 = t2 * 128;
                #pragma unroll
                for (int i = 0; i < 8; i++) {
                    int grow = rb2 + rbw + i * 2;
                    float4 v = (grow < N) ? x4[(size_t)grow * 64 + c2 * 16 + ldq]
                                          : make_float4(0.f, 0.f, 0.f, 0.f);
                    half2 h0 = __floats2half2_rn(v.x, v.y);
                    half2 h1 = __floats2half2_rn(v.z, v.w);
                    ph[i] = make_uint2(*(uint32_t*)&h0, *(uint32_t*)&h1);
                }
            }
            // ---- MMA on current buffer; B fragments double-buffered
            const uint32_t xab = xlaneA + cur * XBUFB;
            const uint32_t bab = blaneB + kc * 128;
            uint32_t bfc[4], bfn[4];
            ldm4(bfc, bab);                       // (ks8=0, ntp=0)
            #pragma unroll
            for (int ks8 = 0; ks8 < 4; ks8++) {
                uint32_t a0[4], a1[4];
                ldm4(a0, xab + ks8 * 32);
                ldm4(a1, xab + ks8 * 32 + 16 * XSTB);
                #pragma unroll
                for (int ntp = 0; ntp < 4; ntp++) {
                    // prefetch next B fragment BEFORE the dependent MMAs
                    if (ntp < 3)
                        ldm4(bfn, bab + ks8 * 32 + (ntp + 1) * (16 * WSTB));
                    else if (ks8 < 3)
                        ldm4(bfn, bab + (ks8 + 1) * 32);
                    mma16816(acc[2*ntp    ][0], a0, bfc[0], bfc[1]);
                    mma16816(acc[2*ntp    ][1], a1, bfc[0], bfc[1]);
                    mma16816(acc[2*ntp + 1][0], a0, bfc[2], bfc[3]);
                    mma16816(acc[2*ntp + 1][1], a1, bfc[2], bfc[3]);
                    bfc[0] = bfn[0]; bfc[1] = bfn[1];
                    bfc[2] = bfn[2]; bfc[3] = bfn[3];
                }
            }
            bar_pair(barid);  // pair done with buf cur; STS of nbuf visible
        }

        // Epilogue: tanh (MUFU) + H->2 projection; quad reduce; pair exchange
        float yv[2][2] = {{0.f,0.f},{0.f,0.f}};
        float zv[2][2] = {{0.f,0.f},{0.f,0.f}};
        #pragma unroll
        for (int nt = 0; nt < 8; nt++) {
            #pragma unroll
            for (int j = 0; j < 2; j++) {
                int h = (hb + nt) * 8 + qq + j;
                float bb = sb1[h], wva = sw2[2*h], wvb = sw2[2*h + 1];
                #pragma unroll
                for (int g = 0; g < 2; g++) {
                    float t0 = tanh_approx(acc[nt][g][j] + bb);
                    yv[g][0] += t0 * wva; zv[g][0] += t0 * wvb;
                    float t1 = tanh_approx(acc[nt][g][2 + j] + bb);
                    yv[g][1] += t1 * wva; zv[g][1] += t1 * wvb;
                }
            }
        }
        #pragma unroll
        for (int o = 1; o < 4; o <<= 1) {
            #pragma unroll
            for (int g = 0; g < 2; g++) {
                yv[g][0] += __shfl_xor_sync(0xffffffff, yv[g][0], o);
                zv[g][0] += __shfl_xor_sync(0xffffffff, zv[g][0], o);
                yv[g][1] += __shfl_xor_sync(0xffffffff, yv[g][1], o);
                zv[g][1] += __shfl_xor_sync(0xffffffff, zv[g][1], o);
            }
        }
        if (w >= 4 && (lane & 3) == 0) {
            #pragma unroll
            for (int g = 0; g < 2; g++) {
                sEp[wa*32 + g*16 + rA    ] = make_float2(yv[g][0], zv[g][0]);
                sEp[wa*32 + g*16 + rA + 8] = make_float2(yv[g][1], zv[g][1]);
            }
        }
        bar_pair(barid);
        if (w < 4 && (lane & 3) == 0) {
            #pragma unroll
            for (int g = 0; g < 2; g++) {
                float2 e0 = sEp[wa*32 + g*16 + rA];
                float2 e1 = sEp[wa*32 + g*16 + rA + 8];
                int gr0 = rowBase + wa*32 + g*16 + rA;
                int gr1 = gr0 + 8;
                if (gr0 < N) { g_y[gr0] = yv[g][0] + e0.x + B20; g_z[gr0] = zv[g][0] + e0.y + B21; }
                if (gr1 < N) { g_y[gr1] = yv[g][1] + e1.x + B20; g_z[gr1] = zv[g][1] + e1.y + B21; }
            }
        }
        t += stride;
    }
}

// ---------------------------------------------------------------------------
// Kernel 2: per-segment stats. |y| <= ||W2[:,0]||_1 ~ 11, so exp(y) is safe
// without max subtraction. Segment offsets via parallel scan. MUFU exp.
// ---------------------------------------------------------------------------
__global__ __launch_bounds__(256) void seg_stats_kernel(const int* __restrict__ lengths, int S)
{
    __shared__ float sred[256];
    __shared__ float sbc[3];
    __shared__ int slen[S_MAX];
    const int s = blockIdx.x, tid = threadIdx.x;

    if (tid < S_MAX) slen[tid] = (tid < S) ? lengths[tid] : 0;
    __syncthreads();
    #pragma unroll
    for (int d = 1; d < S_MAX; d <<= 1) {
        int v = 0;
        if (tid < S_MAX && tid >= d) v = slen[tid - d];
        __syncthreads();
        if (tid < S_MAX) slen[tid] += v;
        __syncthreads();
    }
    const int off = (s == 0) ? 0 : slen[s - 1];
    const int len = lengths[s];
    const float invlen = 1.0f / (float)len;

    float wsum = 0.f, wx = 0.f, zs = 0.f;
    for (int i = tid; i < len; i += 256) {
        float wv = __expf(g_y[off + i]);
        wsum += wv;
        wx   += wv * ((float)(i + 1) * invlen);
        zs   += g_z[off + i];
    }
    sred[tid] = wsum; __syncthreads();
    for (int o = 128; o > 0; o >>= 1) { if (tid < o) sred[tid] += sred[tid+o]; __syncthreads(); }
    if (tid == 0) sbc[0] = sred[0];
    __syncthreads();
    sred[tid] = wx; __syncthreads();
    for (int o = 128; o > 0; o >>= 1) { if (tid < o) sred[tid] += sred[tid+o]; __syncthreads(); }
    if (tid == 0) sbc[1] = sred[0];
    __syncthreads();
    sred[tid] = zs; __syncthreads();
    for (int o = 128; o > 0; o >>= 1) { if (tid < o) sred[tid] += sred[tid+o]; __syncthreads(); }
    if (tid == 0) sbc[2] = sred[0];
    __syncthreads();

    const float mu = sbc[1] / sbc[0];
    const float v  = sbc[2] * invlen;
    const float sd = (v > 20.f) ? v : log1pf(expf(v));   // softplus (precise)
    const float invsd = 1.0f / sd;

    float ps = 0.f;
    for (int i = tid; i < len; i += 256) {
        float xp = (float)(i + 1) * invlen;
        float d = (xp - mu) * invsd;
        ps += __expf(-0.5f * d * d);
    }
    sred[tid] = ps; __syncthreads();
    for (int o = 128; o > 0; o >>= 1) { if (tid < o) sred[tid] += sred[tid+o]; __syncthreads(); }
    if (tid == 0) {
        float psum = sred[0] * (0.3989422804014327f * invsd);
        g_segp[s] = make_float4(mu, sd, psum, 0.f);
        g_offv[s] = off;
    }
}

// ---------------------------------------------------------------------------
// Kernel 3: attn per row + partial of out = seg_sum(attn*x), fused finalize.
//   fp32 x, Grid (NCH x S); 4 row-groups x 64 threads, float4 loads,
//   unroll-8. Last block per segment (atomic counter) sums the NCH
//   deterministic partials into out.
// ---------------------------------------------------------------------------
__global__ __launch_bounds__(256) void attn_out_kernel(
    const float* __restrict__ x, const int* __restrict__ lengths,
    float* __restrict__ attn_out, float* __restrict__ out)
{
    __shared__ float  sattn[256];
    __shared__ float4 sred4[256];
    __shared__ int slast;
    const int s = blockIdx.y, ch = blockIdx.x;
    const int tid = threadIdx.x;
    const int g = tid >> 6;
    const int c = tid & 63;
    const int len = lengths[s];
    const int off = g_offv[s];
    const float4 p = g_segp[s];
    const float mu = p.x, invsd = 1.0f / p.y, psum = p.z;
    const float invlen = 1.0f / (float)len;
    const float coef = 0.3989422804014327f * invsd / (psum + 0.001f);

    float4 acc = make_float4(0.f, 0.f, 0.f, 0.f);
    const int r0 = ch * CROWS;
    #pragma unroll
    for (int tb = 0; tb < CROWS; tb += 256) {
        const int tsz = (CROWS - tb < 256) ? (CROWS - tb) : 256;
        int rbase = r0 + tb;
        if (rbase >= len) break;
        int r = rbase + tid;
        float a = 0.f;
        if (tid < tsz && r < len) {
            float xp = (float)(r + 1) * invlen;
            float d = (xp - mu) * invsd;
            a = __expf(-0.5f * d * d) * coef;
            attn_out[off + r] = a;
        }
        sattn[tid] = a;
        __syncthreads();
        int nrows = len - rbase; if (nrows > tsz) nrows = tsz;
        const float4* __restrict__ xp4 = (const float4*)(x + (size_t)(off + rbase) * 256) + c;
        int j = g;
        for (; j + 28 < nrows; j += 32) {
            float aa[8]; float4 vv[8];
            #pragma unroll
            for (int u = 0; u < 8; u++) { aa[u] = sattn[j + u*4]; vv[u] = xp4[(size_t)(j + u*4) * 64]; }
            #pragma unroll
            for (int u = 0; u < 8; u++) {
                acc.x += aa[u] * vv[u].x; acc.y += aa[u] * vv[u].y;
                acc.z += aa[u] * vv[u].z; acc.w += aa[u] * vv[u].w;
            }
        }
        for (; j < nrows; j += 4) {
            float a0 = sattn[j];
            float4 v0 = xp4[(size_t)j * 64];
            acc.x += a0 * v0.x; acc.y += a0 * v0.y; acc.z += a0 * v0.z; acc.w += a0 * v0.w;
        }
        __syncthreads();
    }
    sred4[tid] = acc;
    __syncthreads();
    if (g == 0) {
        float4 t0 = sred4[c], t1 = sred4[64 + c], t2 = sred4[128 + c], t3 = sred4[192 + c];
        float4 tot = make_float4(t0.x + t1.x + t2.x + t3.x,
                                 t0.y + t1.y + t2.y + t3.y,
                                 t0.z + t1.z + t2.z + t3.z,
                                 t0.w + t1.w + t2.w + t3.w);
        ((float4*)&g_part[(size_t)(s * NCH + ch) * 256])[c] = tot;
    }
    // ---- fused finalize: last chunk-block of this segment sums partials
    __threadfence();
    if (tid == 0) {
        int old = atomicAdd(&g_cnt[s], 1);
        slast = (old == NCH - 1);
    }
    __syncthreads();
    if (slast) {
        float v = 0.f;
        #pragma unroll
        for (int j = 0; j < NCH; j++) v += g_part[(size_t)(s * NCH + j) * 256 + tid];
        out[(size_t)s * 256 + tid] = v;
        if (tid == 0) g_cnt[s] = 0;   // reset for next graph replay
    }
}

// ---------------------------------------------------------------------------
extern "C" void kernel_launch(void* const* d_in, const int* in_sizes, int n_in,
                              void* d_out, int out_size)
{
    const float* x       = (const float*)d_in[0];
    const int*   lengths = (const int*)  d_in[1];
    const float* W1      = (const float*)d_in[2];
    const float* b1      = (const float*)d_in[3];
    const float* W2      = (const float*)d_in[4];
    const float* b2      = (const float*)d_in[5];

    const int N = in_sizes[0] / 256;
    const int S = in_sizes[1];

    float* out  = (float*)d_out;             // (S, 256)
    float* attn = out + (size_t)S * 256;     // (N, 1)

    cudaFuncSetAttribute(gemm_head_kernel,
                         cudaFuncAttributeMaxDynamicSharedMemorySize, SMEM_K1);

    int ntiles = (N + 127) / 128;
    int grid = ntiles < 296 ? ntiles : 296;   // 2 blocks/SM persistent
    gemm_head_kernel<<<grid, 256, SMEM_K1>>>(x, W1, b1, W2, b2, N, ntiles);
    seg_stats_kernel<<<S, 256>>>(lengths, S);
    attn_out_kernel<<<dim3(NCH, S), 256>>>(x, lengths, attn, out);
}

// round 13
// speedup vs baseline: 1.1937x; 1.0002x over previous
#include <cuda_runtime.h>
#include <cuda_fp16.h>
#include <cstdint>

// Problem-shape maxima (S=128 segments, lengths in [1024,3072])
#define NMAX 393216
#define S_MAX 128
#define NCH 8          // attn chunks per segment
#define CROWS 384      // rows per attn chunk (8*384 = 3072 = max len)

__device__ float g_y[NMAX];
__device__ float g_z[NMAX];
__device__ float4 g_segp[S_MAX];
__device__ int   g_offv[S_MAX];
__device__ float g_part[S_MAX * NCH * 256];
__device__ int   g_cnt[S_MAX];   // zero-init at load; self-resetting per call

__device__ __forceinline__ float tanh_approx(float v) {
    float r;
    asm("tanh.approx.f32 %0, %1;" : "=f"(r) : "f"(v));
    return r;
}
__device__ __forceinline__ uint32_t smem_u32(const void* p) {
    uint32_t a;
    asm("{ .reg .u64 t; cvta.to.shared.u64 t, %1; cvt.u32.u64 %0, t; }" : "=r"(a) : "l"(p));
    return a;
}
__device__ __forceinline__ void ldm4(uint32_t* r, uint32_t addr) {
    asm volatile("ldmatrix.sync.aligned.m8n8.x4.shared.b16 {%0,%1,%2,%3}, [%4];"
        : "=r"(r[0]), "=r"(r[1]), "=r"(r[2]), "=r"(r[3]) : "r"(addr));
}
// f16-accumulate HMMA: C/D = 2 regs (f16x2), 2x tensor-pipe rate vs f32 accum
__device__ __forceinline__ void mma16816h(uint32_t* c, const uint32_t* a,
                                          uint32_t b0, uint32_t b1) {
    asm volatile("mma.sync.aligned.m16n8k16.row.col.f16.f16.f16.f16 "
        "{%0,%1}, {%2,%3,%4,%5}, {%6,%7}, {%0,%1};"
        : "+r"(c[0]), "+r"(c[1])
        : "r"(a[0]), "r"(a[1]), "r"(a[2]), "r"(a[3]), "r"(b0), "r"(b1));
}
__device__ __forceinline__ void bar_pair(int id) {
    asm volatile("bar.sync %0, 64;" :: "r"(id) : "memory");
}

// ---------------------------------------------------------------------------
// Kernel 1 (v11 = v10 + f16 accumulation): persistent fused GEMM + head,
// HMMA + ldmatrix, PAIR-DECOUPLED.
//   256 threads / 8 warps, 2 blocks per SM. Warp pair (w, w+4) owns A-row
//   quarter wa = w&3 (32 rows); w<4 -> h[0:64), w>=4 -> h[64:128).
//   Pair-private A staging; bar.sync(1+wa, 64) only; double-buffered A
//   chunks; LDG prefetch 2 chunks ahead; B fragments double-buffered.
//   NEW: f16 accumulators (acc[8][2][2] u32 = 32 regs vs 64) -> reg slack
//   under the 128 cap + 2x HMMA rate. Row y/z error ~2e-3 washes through the
//   segment stats to ~1e-5 final.
// ---------------------------------------------------------------------------
#define XSTB 144          // x row stride, bytes (64 halves + 8 pad)
#define WSTB 528          // W1 row stride, bytes (256 halves + 8 pad)
#define WST  264          // W1 row stride, halves
#define XBUFB (128 * XSTB)           // 18432 bytes per x buffer
#define W1OFF (2 * XBUFB)            // 36864
#define FOFF  (W1OFF + 128 * WSTB)   // 104448
#define SMEM_K1 (FOFF + 512 + 1024 + 1024)

__global__ __launch_bounds__(256, 2) void gemm_head_kernel(
    const float* __restrict__ x, const float* __restrict__ W1,
    const float* __restrict__ b1, const float* __restrict__ W2,
    const float* __restrict__ b2, int N, int ntiles)
{
    extern __shared__ char smem[];
    half*   w1s = (half*)(smem + W1OFF);
    float*  sb1 = (float*)(smem + FOFF);
    float*  sw2 = sb1 + 128;
    float2* sEp = (float2*)(sw2 + 256);

    const int tid  = threadIdx.x;
    const int lane = tid & 31;
    const int w    = tid >> 5;       // 0..7
    const int wa   = w & 3;          // pair id / A-row quarter
    const int hb   = (w >> 2) * 8;   // h-tile base (units of 8 columns)
    const int barid = 1 + wa;

    // Stage W1 transposed (h-major, k contiguous) as fp16 — once per block
    for (int idx = tid; idx < 256 * 128; idx += 256) {
        int k = idx >> 7, h = idx & 127;
        w1s[h * WST + k] = __float2half(W1[idx]);
    }
    if (tid < 128) sb1[tid] = b1[tid];
    sw2[tid] = W2[tid];

    const float B20 = __ldg(b2), B21 = __ldg(b2 + 1);
    const int stride = gridDim.x;
    const float4* __restrict__ x4 = (const float4*)x;

    // LDG/STS pattern: pair (w, w+4) stages rows [wa*32, wa*32+32);
    // this warp handles 16 of them: 2 rows per iteration, 8 iterations.
    const int rbw = wa * 32 + (w >> 2) * 16 + (lane >> 4);  // + i*2
    const int ldq = lane & 15;                               // float4 col

    // ldmatrix per-lane address constants (validated)
    const uint32_t sbase = smem_u32(smem);
    const uint32_t aoffc = ((lane >> 3) & 1) * (8 * XSTB) + (lane & 7) * XSTB + (lane >> 4) * 16;
    const uint32_t boffc = (lane >> 4) * (8 * WSTB) + (lane & 7) * WSTB + ((lane >> 3) & 1) * 16;
    const uint32_t xlaneA = sbase + wa * 32 * XSTB + aoffc;
    const uint32_t blaneB = sbase + W1OFF + hb * (8 * WSTB) + boffc;

    const int rA = lane >> 2;         // epilogue row-in-group
    const int qq = (lane & 3) * 2;    // epilogue col pair

    uint2 ph[8];   // prefetched chunk, already fp16 (half2 pairs)
    int t = blockIdx.x;   // grid <= ntiles

    __syncthreads();   // W1 staged (only block-wide sync)

    // ---- prologue: buf0 <- chunk0(t); ph <- chunk1(t)
    #pragma unroll
    for (int i = 0; i < 8; i++) {
        int grow = t * 128 + rbw + i * 2;
        float4 v = (grow < N) ? x4[(size_t)grow * 64 + ldq]
                              : make_float4(0.f, 0.f, 0.f, 0.f);
        half2 h0 = __floats2half2_rn(v.x, v.y);
        half2 h1 = __floats2half2_rn(v.z, v.w);
        *(uint2*)(smem + (rbw + i * 2) * XSTB + ldq * 8) =
            make_uint2(*(uint32_t*)&h0, *(uint32_t*)&h1);
    }
    #pragma unroll
    for (int i = 0; i < 8; i++) {
        int grow = t * 128 + rbw + i * 2;
        float4 v = (grow < N) ? x4[(size_t)grow * 64 + 16 + ldq]
                              : make_float4(0.f, 0.f, 0.f, 0.f);
        half2 h0 = __floats2half2_rn(v.x, v.y);
        half2 h1 = __floats2half2_rn(v.z, v.w);
        ph[i] = make_uint2(*(uint32_t*)&h0, *(uint32_t*)&h1);
    }
    bar_pair(barid);   // buf0 visible to the pair

    while (t < ntiles) {
        const int rowBase = t * 128;
        uint32_t acc[8][2][2];    // f16x2 accumulators
        #pragma unroll
        for (int i = 0; i < 8; i++)
            #pragma unroll
            for (int g = 0; g < 2; g++) { acc[i][g][0] = 0u; acc[i][g][1] = 0u; }

        #pragma unroll
        for (int kc = 0; kc < 4; kc++) {
            const int cur = kc & 1;
            // ---- STS: ph (chunk kc+1) -> other buffer (pair's rows only)
            int t1 = t; if (kc == 3) t1 = t + stride;
            if (t1 < ntiles) {
                char* xb = smem + (((kc + 1) & 1) * XBUFB);
                #pragma unroll
                for (int i = 0; i < 8; i++)
                    *(uint2*)(xb + (rbw + i * 2) * XSTB + ldq * 8) = ph[i];
            }
            // ---- LDG: chunk kc+2 -> ph (convert to fp16 at load)
            int t2 = t, c2 = kc + 2;
            if (kc >= 2) { t2 = t + stride; c2 = kc - 2; }
            if (t2 < ntiles) {
                int rb2 = t2 * 128;
                #pragma unroll
                for (int i = 0; i < 8; i++) {
                    int grow = rb2 + rbw + i * 2;
                    float4 v = (grow < N) ? x4[(size_t)grow * 64 + c2 * 16 + ldq]
                                          : make_float4(0.f, 0.f, 0.f, 0.f);
                    half2 h0 = __floats2half2_rn(v.x, v.y);
                    half2 h1 = __floats2half2_rn(v.z, v.w);
                    ph[i] = make_uint2(*(uint32_t*)&h0, *(uint32_t*)&h1);
                }
            }
            // ---- MMA on current buffer; B fragments double-buffered
            const uint32_t xab = xlaneA + cur * XBUFB;
            const uint32_t bab = blaneB + kc * 128;
            uint32_t bfc[4], bfn[4];
            ldm4(bfc, bab);                       // (ks8=0, ntp=0)
            #pragma unroll
            for (int ks8 = 0; ks8 < 4; ks8++) {
                uint32_t a0[4], a1[4];
                ldm4(a0, xab + ks8 * 32);
                ldm4(a1, xab + ks8 * 32 + 16 * XSTB);
                #pragma unroll
                for (int ntp = 0; ntp < 4; ntp++) {
                    // prefetch next B fragment BEFORE the dependent MMAs
                    if (ntp < 3)
                        ldm4(bfn, bab + ks8 * 32 + (ntp + 1) * (16 * WSTB));
                    else if (ks8 < 3)
                        ldm4(bfn, bab + (ks8 + 1) * 32);
                    mma16816h(acc[2*ntp    ][0], a0, bfc[0], bfc[1]);
                    mma16816h(acc[2*ntp    ][1], a1, bfc[0], bfc[1]);
                    mma16816h(acc[2*ntp + 1][0], a0, bfc[2], bfc[3]);
                    mma16816h(acc[2*ntp + 1][1], a1, bfc[2], bfc[3]);
                    bfc[0] = bfn[0]; bfc[1] = bfn[1];
                    bfc[2] = bfn[2]; bfc[3] = bfn[3];
                }
            }
            bar_pair(barid);  // pair done with buf cur; STS of nbuf visible
        }

        // Epilogue: unpack f16 accs, tanh (MUFU) + H->2 projection;
        // quad reduce; pair exchange.
        // acc[nt][g][0] = {row rA,   cols qq, qq+1}; [1] = {row rA+8, same}
        float yv[2][2] = {{0.f,0.f},{0.f,0.f}};
        float zv[2][2] = {{0.f,0.f},{0.f,0.f}};
        #pragma unroll
        for (int nt = 0; nt < 8; nt++) {
            const int h0 = (hb + nt) * 8 + qq;
            const int h1 = h0 + 1;
            const float bb0 = sb1[h0], wa0 = sw2[2*h0], wb0 = sw2[2*h0 + 1];
            const float bb1 = sb1[h1], wa1 = sw2[2*h1], wb1 = sw2[2*h1 + 1];
            #pragma unroll
            for (int g = 0; g < 2; g++) {
                float2 f0 = __half22float2(*(half2*)&acc[nt][g][0]);
                float2 f1 = __half22float2(*(half2*)&acc[nt][g][1]);
                float t00 = tanh_approx(f0.x + bb0);
                float t01 = tanh_approx(f0.y + bb1);
                float t10 = tanh_approx(f1.x + bb0);
                float t11 = tanh_approx(f1.y + bb1);
                yv[g][0] += t00 * wa0 + t01 * wa1;
                zv[g][0] += t00 * wb0 + t01 * wb1;
                yv[g][1] += t10 * wa0 + t11 * wa1;
                zv[g][1] += t10 * wb0 + t11 * wb1;
            }
        }
        #pragma unroll
        for (int o = 1; o < 4; o <<= 1) {
            #pragma unroll
            for (int g = 0; g < 2; g++) {
                yv[g][0] += __shfl_xor_sync(0xffffffff, yv[g][0], o);
                zv[g][0] += __shfl_xor_sync(0xffffffff, zv[g][0], o);
                yv[g][1] += __shfl_xor_sync(0xffffffff, yv[g][1], o);
                zv[g][1] += __shfl_xor_sync(0xffffffff, zv[g][1], o);
            }
        }
        if (w >= 4 && (lane & 3) == 0) {
            #pragma unroll
            for (int g = 0; g < 2; g++) {
                sEp[wa*32 + g*16 + rA    ] = make_float2(yv[g][0], zv[g][0]);
                sEp[wa*32 + g*16 + rA + 8] = make_float2(yv[g][1], zv[g][1]);
            }
        }
        bar_pair(barid);
        if (w < 4 && (lane & 3) == 0) {
            #pragma unroll
            for (int g = 0; g < 2; g++) {
                float2 e0 = sEp[wa*32 + g*16 + rA];
                float2 e1 = sEp[wa*32 + g*16 + rA + 8];
                int gr0 = rowBase + wa*32 + g*16 + rA;
                int gr1 = gr0 + 8;
                if (gr0 < N) { g_y[gr0] = yv[g][0] + e0.x + B20; g_z[gr0] = zv[g][0] + e0.y + B21; }
                if (gr1 < N) { g_y[gr1] = yv[g][1] + e1.x + B20; g_z[gr1] = zv[g][1] + e1.y + B21; }
            }
        }
        t += stride;
    }
}

// ---------------------------------------------------------------------------
// Kernel 2: per-segment stats. |y| <= ||W2[:,0]||_1 ~ 11, so exp(y) is safe
// without max subtraction. Segment offsets via parallel scan. MUFU exp.
// ---------------------------------------------------------------------------
__global__ __launch_bounds__(256) void seg_stats_kernel(const int* __restrict__ lengths, int S)
{
    __shared__ float sred[256];
    __shared__ float sbc[3];
    __shared__ int slen[S_MAX];
    const int s = blockIdx.x, tid = threadIdx.x;

    if (tid < S_MAX) slen[tid] = (tid < S) ? lengths[tid] : 0;
    __syncthreads();
    #pragma unroll
    for (int d = 1; d < S_MAX; d <<= 1) {
        int v = 0;
        if (tid < S_MAX && tid >= d) v = slen[tid - d];
        __syncthreads();
        if (tid < S_MAX) slen[tid] += v;
        __syncthreads();
    }
    const int off = (s == 0) ? 0 : slen[s - 1];
    const int len = lengths[s];
    const float invlen = 1.0f / (float)len;

    float wsum = 0.f, wx = 0.f, zs = 0.f;
    for (int i = tid; i < len; i += 256) {
        float wv = __expf(g_y[off + i]);
        wsum += wv;
        wx   += wv * ((float)(i + 1) * invlen);
        zs   += g_z[off + i];
    }
    sred[tid] = wsum; __syncthreads();
    for (int o = 128; o > 0; o >>= 1) { if (tid < o) sred[tid] += sred[tid+o]; __syncthreads(); }
    if (tid == 0) sbc[0] = sred[0];
    __syncthreads();
    sred[tid] = wx; __syncthreads();
    for (int o = 128; o > 0; o >>= 1) { if (tid < o) sred[tid] += sred[tid+o]; __syncthreads(); }
    if (tid == 0) sbc[1] = sred[0];
    __syncthreads();
    sred[tid] = zs; __syncthreads();
    for (int o = 128; o > 0; o >>= 1) { if (tid < o) sred[tid] += sred[tid+o]; __syncthreads(); }
    if (tid == 0) sbc[2] = sred[0];
    __syncthreads();

    const float mu = sbc[1] / sbc[0];
    const float v  = sbc[2] * invlen;
    const float sd = (v > 20.f) ? v : log1pf(expf(v));   // softplus (precise)
    const float invsd = 1.0f / sd;

    float ps = 0.f;
    for (int i = tid; i < len; i += 256) {
        float xp = (float)(i + 1) * invlen;
        float d = (xp - mu) * invsd;
        ps += __expf(-0.5f * d * d);
    }
    sred[tid] = ps; __syncthreads();
    for (int o = 128; o > 0; o >>= 1) { if (tid < o) sred[tid] += sred[tid+o]; __syncthreads(); }
    if (tid == 0) {
        float psum = sred[0] * (0.3989422804014327f * invsd);
        g_segp[s] = make_float4(mu, sd, psum, 0.f);
        g_offv[s] = off;
    }
}

// ---------------------------------------------------------------------------
// Kernel 3: attn per row + partial of out = seg_sum(attn*x), fused finalize.
//   fp32 x, Grid (NCH x S); 4 row-groups x 64 threads, float4 loads,
//   unroll-8. Last block per segment (atomic counter) sums the NCH
//   deterministic partials into out.
// ---------------------------------------------------------------------------
__global__ __launch_bounds__(256) void attn_out_kernel(
    const float* __restrict__ x, const int* __restrict__ lengths,
    float* __restrict__ attn_out, float* __restrict__ out)
{
    __shared__ float  sattn[256];
    __shared__ float4 sred4[256];
    __shared__ int slast;
    const int s = blockIdx.y, ch = blockIdx.x;
    const int tid = threadIdx.x;
    const int g = tid >> 6;
    const int c = tid & 63;
    const int len = lengths[s];
    const int off = g_offv[s];
    const float4 p = g_segp[s];
    const float mu = p.x, invsd = 1.0f / p.y, psum = p.z;
    const float invlen = 1.0f / (float)len;
    const float coef = 0.3989422804014327f * invsd / (psum + 0.001f);

    float4 acc = make_float4(0.f, 0.f, 0.f, 0.f);
    const int r0 = ch * CROWS;
    #pragma unroll
    for (int tb = 0; tb < CROWS; tb += 256) {
        const int tsz = (CROWS - tb < 256) ? (CROWS - tb) : 256;
        int rbase = r0 + tb;
        if (rbase >= len) break;
        int r = rbase + tid;
        float a = 0.f;
        if (tid < tsz && r < len) {
            float xp = (float)(r + 1) * invlen;
            float d = (xp - mu) * invsd;
            a = __expf(-0.5f * d * d) * coef;
            attn_out[off + r] = a;
        }
        sattn[tid] = a;
        __syncthreads();
        int nrows = len - rbase; if (nrows > tsz) nrows = tsz;
        const float4* __restrict__ xp4 = (const float4*)(x + (size_t)(off + rbase) * 256) + c;
        int j = g;
        for (; j + 28 < nrows; j += 32) {
            float aa[8]; float4 vv[8];
            #pragma unroll
            for (int u = 0; u < 8; u++) { aa[u] = sattn[j + u*4]; vv[u] = xp4[(size_t)(j + u*4) * 64]; }
            #pragma unroll
            for (int u = 0; u < 8; u++) {
                acc.x += aa[u] * vv[u].x; acc.y += aa[u] * vv[u].y;
                acc.z += aa[u] * vv[u].z; acc.w += aa[u] * vv[u].w;
            }
        }
        for (; j < nrows; j += 4) {
            float a0 = sattn[j];
            float4 v0 = xp4[(size_t)j * 64];
            acc.x += a0 * v0.x; acc.y += a0 * v0.y; acc.z += a0 * v0.z; acc.w += a0 * v0.w;
        }
        __syncthreads();
    }
    sred4[tid] = acc;
    __syncthreads();
    if (g == 0) {
        float4 t0 = sred4[c], t1 = sred4[64 + c], t2 = sred4[128 + c], t3 = sred4[192 + c];
        float4 tot = make_float4(t0.x + t1.x + t2.x + t3.x,
                                 t0.y + t1.y + t2.y + t3.y,
                                 t0.z + t1.z + t2.z + t3.z,
                                 t0.w + t1.w + t2.w + t3.w);
        ((float4*)&g_part[(size_t)(s * NCH + ch) * 256])[c] = tot;
    }
    // ---- fused finalize: last chunk-block of this segment sums partials
    __threadfence();
    if (tid == 0) {
        int old = atomicAdd(&g_cnt[s], 1);
        slast = (old == NCH - 1);
    }
    __syncthreads();
    if (slast) {
        float v = 0.f;
        #pragma unroll
        for (int j = 0; j < NCH; j++) v += g_part[(size_t)(s * NCH + j) * 256 + tid];
        out[(size_t)s * 256 + tid] = v;
        if (tid == 0) g_cnt[s] = 0;   // reset for next graph replay
    }
}

// ---------------------------------------------------------------------------
extern "C" void kernel_launch(void* const* d_in, const int* in_sizes, int n_in,
                              void* d_out, int out_size)
{
    const float* x       = (const float*)d_in[0];
    const int*   lengths = (const int*)  d_in[1];
    const float* W1      = (const float*)d_in[2];
    const float* b1      = (const float*)d_in[3];
    const float* W2      = (const float*)d_in[4];
    const float* b2      = (const float*)d_in[5];

    const int N = in_sizes[0] / 256;
    const int S = in_sizes[1];

    float* out  = (float*)d_out;             // (S, 256)
    float* attn = out + (size_t)S * 256;     // (N, 1)

    cudaFuncSetAttribute(gemm_head_kernel,
                         cudaFuncAttributeMaxDynamicSharedMemorySize, SMEM_K1);

    int ntiles = (N + 127) / 128;
    int grid = ntiles < 296 ? ntiles : 296;   // 2 blocks/SM persistent
    gemm_head_kernel<<<grid, 256, SMEM_K1>>>(x, W1, b1, W2, b2, N, ntiles);
    seg_stats_kernel<<<S, 256>>>(lengths, S);
    attn_out_kernel<<<dim3(NCH, S), 256>>>(x, lengths, attn, out);
}